// round 4
// baseline (speedup 1.0000x reference)
#include <cuda_runtime.h>
#include <cuda_pipeline.h>
#include <math.h>
#include <stdint.h>

#define B_   4
#define LQ_  2048
#define LK_  2048
#define XS_  1024
#define PD_  128
#define NSPLIT 2
#define NT_SPLIT (LK_ / 64 / NSPLIT)   // 16 K-tiles per split

// Scratch (device globals: no allocation allowed). g_q/k/v hold TF32-rounded
// projections; g_po/g_ml hold split-KV partial outputs.
__device__ float g_q[B_ * LQ_ * PD_];
__device__ float g_k[B_ * LK_ * PD_];
__device__ float g_v[B_ * LK_ * PD_];
__device__ float g_po[NSPLIT * B_ * LQ_ * PD_];
__device__ float g_ml[NSPLIT * B_ * LQ_ * 2];

__device__ __forceinline__ float to_tf32(float x) {
    float r;
    asm("cvt.rna.tf32.f32 %0, %1;" : "=f"(r) : "f"(x));
    return r;
}

// D += A*B, m16n8k8 tf32; a,b are raw tf32 bit patterns.
__device__ __forceinline__ void mma_tf32u(float* c, const uint32_t* a, const uint32_t* b) {
    asm volatile(
        "mma.sync.aligned.m16n8k8.row.col.f32.tf32.tf32.f32 "
        "{%0,%1,%2,%3}, {%4,%5,%6,%7}, {%8,%9}, {%0,%1,%2,%3};\n"
        : "+f"(c[0]), "+f"(c[1]), "+f"(c[2]), "+f"(c[3])
        : "r"(a[0]), "r"(a[1]), "r"(a[2]), "r"(a[3]), "r"(b[0]), "r"(b[1]));
}

// ldmatrix x4: each 8x4-tf32 sub-tile addressed as an 8x8-b16 tile.
__device__ __forceinline__ void ldsm4(uint32_t addr, uint32_t* r) {
    asm volatile("ldmatrix.sync.aligned.m8n8.x4.shared.b16 {%0,%1,%2,%3}, [%4];"
                 : "=r"(r[0]), "=r"(r[1]), "=r"(r[2]), "=r"(r[3])
                 : "r"(addr));
}

// ---------------------------------------------------------------------------
// Projection GEMM (tf32, ldmatrix): C[8192,128] = A[8192,1024]@W[1024,128]+b
// grid (64,3), 256 thr = 8 warps (4m x 2n). Tile 128x128, BK=32.
// As[m][k] pitch 36; Wt[n][k] pitch 36 (W transposed at store for LDSM B-frags).
// ---------------------------------------------------------------------------
#define PAP 36

__global__ __launch_bounds__(256) void proj_kernel(
    const float* __restrict__ x, const float* __restrict__ y,
    const float* __restrict__ Wq, const float* __restrict__ bq,
    const float* __restrict__ Wk, const float* __restrict__ bk,
    const float* __restrict__ Wv, const float* __restrict__ bv)
{
    const float* A; const float* W; const float* bias; float* C;
    if (blockIdx.y == 0)      { A = x; W = Wq; bias = bq; C = g_q; }
    else if (blockIdx.y == 1) { A = y; W = Wk; bias = bk; C = g_k; }
    else                      { A = y; W = Wv; bias = bv; C = g_v; }

    __shared__ float As[128 * PAP];
    __shared__ float Wt[128 * PAP];

    const int tid  = threadIdx.x;
    const int wid  = tid >> 5;
    const int lane = tid & 31;
    const int lr = lane >> 2, lc = lane & 3;
    const int g8 = lane >> 3, r8 = lane & 7;
    const int rw = (wid & 3) * 32;
    const int cw = (wid >> 2) * 64;
    const int row0 = blockIdx.x * 128;

    const uint32_t as_u = (uint32_t)__cvta_generic_to_shared(As);
    const uint32_t wt_u = (uint32_t)__cvta_generic_to_shared(Wt);
    // A-frag (mf=0): rows rw + (g8&1)*8 + r8, col chunk (g8>>1)*4
    const int a_off = (rw + (g8 & 1) * 8 + r8) * PAP + (g8 >> 1) * 4;
    // W B-frag: rows cw + (g8>>1)*8 + r8, col chunk (g8&1)*4
    const int w_off = (cw + (g8 >> 1) * 8 + r8) * PAP + (g8 & 1) * 4;

    float4 rA[4], rW[4];
    #pragma unroll
    for (int i = 0; i < 4; i++) {
        const int g = tid + i * 256;
        rA[i] = *(const float4*)(A + (size_t)(row0 + (g >> 3)) * XS_ + (g & 7) * 4);
        rW[i] = *(const float4*)(W + (size_t)(g & 31) * PD_ + (g >> 5) * 4);
    }

    float acc[2][8][4];
    #pragma unroll
    for (int mf = 0; mf < 2; mf++)
        #pragma unroll
        for (int nf = 0; nf < 8; nf++)
            #pragma unroll
            for (int r = 0; r < 4; r++) acc[mf][nf][r] = 0.0f;

    for (int c = 0; c < 32; c++) {
        __syncthreads();
        #pragma unroll
        for (int i = 0; i < 4; i++) {
            const int g = tid + i * 256;
            float4 ta;
            ta.x = to_tf32(rA[i].x); ta.y = to_tf32(rA[i].y);
            ta.z = to_tf32(rA[i].z); ta.w = to_tf32(rA[i].w);
            *(float4*)&As[(g >> 3) * PAP + (g & 7) * 4] = ta;
            const int wk = g & 31, wn = (g >> 5) * 4;
            Wt[(wn + 0) * PAP + wk] = to_tf32(rW[i].x);
            Wt[(wn + 1) * PAP + wk] = to_tf32(rW[i].y);
            Wt[(wn + 2) * PAP + wk] = to_tf32(rW[i].z);
            Wt[(wn + 3) * PAP + wk] = to_tf32(rW[i].w);
        }
        __syncthreads();

        if (c < 31) {
            const int k0 = (c + 1) * 32;
            #pragma unroll
            for (int i = 0; i < 4; i++) {
                const int g = tid + i * 256;
                rA[i] = *(const float4*)(A + (size_t)(row0 + (g >> 3)) * XS_ + k0 + (g & 7) * 4);
                rW[i] = *(const float4*)(W + (size_t)(k0 + (g & 31)) * PD_ + (g >> 5) * 4);
            }
        }

        #pragma unroll
        for (int kf = 0; kf < 4; kf++) {
            const int k = kf * 8;
            uint32_t a0[4], a1[4];
            ldsm4(as_u + (uint32_t)(a_off + k) * 4, a0);
            ldsm4(as_u + (uint32_t)(a_off + 16 * PAP + k) * 4, a1);
            #pragma unroll
            for (int nfp = 0; nfp < 4; nfp++) {
                uint32_t bw[4];
                ldsm4(wt_u + (uint32_t)(w_off + nfp * 16 * PAP + k) * 4, bw);
                mma_tf32u(acc[0][2 * nfp],     a0, bw);
                mma_tf32u(acc[0][2 * nfp + 1], a0, bw + 2);
                mma_tf32u(acc[1][2 * nfp],     a1, bw);
                mma_tf32u(acc[1][2 * nfp + 1], a1, bw + 2);
            }
        }
    }

    #pragma unroll
    for (int mf = 0; mf < 2; mf++) {
        #pragma unroll
        for (int nf = 0; nf < 8; nf++) {
            const int row = row0 + rw + mf * 16 + lr;
            const int col = cw + nf * 8 + 2 * lc;
            const float2 bb = *(const float2*)(bias + col);
            float2 o0, o1;
            o0.x = to_tf32(acc[mf][nf][0] + bb.x);
            o0.y = to_tf32(acc[mf][nf][1] + bb.y);
            o1.x = to_tf32(acc[mf][nf][2] + bb.x);
            o1.y = to_tf32(acc[mf][nf][3] + bb.y);
            *(float2*)(C + (size_t)row * PD_ + col) = o0;
            *(float2*)(C + (size_t)(row + 8) * PD_ + col) = o1;
        }
    }
}

// ---------------------------------------------------------------------------
// Flash attention, tf32 + ldmatrix, split-KV x2, post-softmax triu(k=1) mask.
// grid (16, 4, 2), 256 thr = 8 warps; warp w owns rows w*16..w*16+15.
// Qs[128][132] (once), Ks 2x[64][132] (cp.async dbl buf), Vt[128 d][68 j]
// (LDG->reg->transposed STS, single buf), Ps[128][68].
// Emits unnormalized partial O + per-row (m,l); combine_kernel merges.
// ---------------------------------------------------------------------------
#define AQP 132
#define AVP 68
#define APP 68
#define SQ 0
#define SK (128 * AQP)
#define SV (SK + 2 * 64 * AQP)
#define SP (SV + 128 * AVP)
#define ATT_SMEM_FLOATS (SP + 128 * APP)   // 51200
#define ATT_SMEM_BYTES (ATT_SMEM_FLOATS * 4)  // 204800

__global__ __launch_bounds__(256) void attn_kernel(const int* __restrict__ maskp)
{
    extern __shared__ float sm[];
    float* Qs = sm + SQ;
    float* Ks = sm + SK;
    float* Vt = sm + SV;
    float* Ps = sm + SP;

    const int b = blockIdx.y;
    const int qbase = blockIdx.x * 128;
    const int split = blockIdx.z;
    const int ts = split * NT_SPLIT;

    const float* Qg = g_q + ((size_t)b * LQ_ + qbase) * PD_;
    const float* Kg = g_k + (size_t)b * LK_ * PD_;
    const float* Vg = g_v + (size_t)b * LK_ * PD_;

    const int tid  = threadIdx.x;
    const int wid  = tid >> 5;
    const int lane = tid & 31;
    const int lr = lane >> 2, lc = lane & 3;
    const int g8 = lane >> 3, r8 = lane & 7;
    const int r0w = wid * 16;
    const int msk = *maskp;
    const float SCALE = 0.0883883476483184f;  // 1/sqrt(128)

    const uint32_t qs_u = (uint32_t)__cvta_generic_to_shared(Qs);
    const uint32_t ks_u = (uint32_t)__cvta_generic_to_shared(Ks);
    const uint32_t vt_u = (uint32_t)__cvta_generic_to_shared(Vt);
    const uint32_t ps_u = (uint32_t)__cvta_generic_to_shared(Ps);

    // LDSM per-thread base offsets (float elements)
    const int q_off = (r0w + (g8 & 1) * 8 + r8) * AQP + (g8 >> 1) * 4;  // A-frag Q
    const int k_off = ((g8 >> 1) * 8 + r8) * AQP + (g8 & 1) * 4;        // B-frag K
    const int p_off = (r0w + (g8 & 1) * 8 + r8) * APP + (g8 >> 1) * 4;  // A-frag P
    const int v_off = ((g8 >> 1) * 8 + r8) * AVP + (g8 & 1) * 4;        // B-frag Vt

    // Prologue: Q (16 chunks/thread) + K tile ts (8 chunks/thread) via cp.async
    #pragma unroll
    for (int i = 0; i < 16; i++) {
        const int g = tid + i * 256;
        const int row = g >> 5, d4 = (g & 31) * 4;
        __pipeline_memcpy_async(&Qs[row * AQP + d4], Qg + (size_t)row * PD_ + d4, 16);
    }
    #pragma unroll
    for (int i = 0; i < 8; i++) {
        const int g = tid + i * 256;
        const int j = g >> 5, d4 = (g & 31) * 4;
        __pipeline_memcpy_async(&Ks[j * AQP + d4],
                                Kg + ((size_t)ts * 64 + j) * PD_ + d4, 16);
    }
    __pipeline_commit();

    // V tile ts -> registers (transposed STS happens at loop top)
    float4 vreg[8];
    {
        const float* Vsrc = Vg + (size_t)ts * 64 * PD_;
        #pragma unroll
        for (int i = 0; i < 8; i++) {
            const int g = tid + i * 256;
            const int j = g & 63, dc = g >> 6;
            vreg[i] = *(const float4*)(Vsrc + (size_t)j * PD_ + dc * 4);
        }
    }

    float oacc[16][4];
    #pragma unroll
    for (int nf = 0; nf < 16; nf++)
        #pragma unroll
        for (int r = 0; r < 4; r++) oacc[nf][r] = 0.0f;
    float m_run[2] = {-1e30f, -1e30f};
    float l_run[2] = {0.0f, 0.0f};

    for (int tt = 0; tt < NT_SPLIT; tt++) {
        const int t = ts + tt;
        const int kbase = t * 64;
        const uint32_t kb_u = ks_u + (uint32_t)(tt & 1) * (64 * AQP * 4);

        __pipeline_wait_prior(0);
        __syncthreads();   // K(t) visible; all warps done with Vt/K(prev)

        // Stage V(t) into Vt (transposed [d][j])
        #pragma unroll
        for (int i = 0; i < 8; i++) {
            const int g = tid + i * 256;
            const int j = g & 63, dc = g >> 6;
            Vt[(dc * 4 + 0) * AVP + j] = vreg[i].x;
            Vt[(dc * 4 + 1) * AVP + j] = vreg[i].y;
            Vt[(dc * 4 + 2) * AVP + j] = vreg[i].z;
            Vt[(dc * 4 + 3) * AVP + j] = vreg[i].w;
        }
        if (tt + 1 < NT_SPLIT) {
            float* Kn = Ks + ((tt + 1) & 1) * (64 * AQP);
            const float* Ksrc = Kg + (size_t)(kbase + 64) * PD_;
            #pragma unroll
            for (int i = 0; i < 8; i++) {
                const int g = tid + i * 256;
                const int j = g >> 5, d4 = (g & 31) * 4;
                __pipeline_memcpy_async(&Kn[j * AQP + d4], Ksrc + (size_t)j * PD_ + d4, 16);
            }
            __pipeline_commit();
        }
        __syncthreads();   // Vt visible

        // Prefetch V(t+1) to regs (overlaps QK+softmax)
        if (tt + 1 < NT_SPLIT) {
            const float* Vsrc = Vg + (size_t)(kbase + 64) * PD_;
            #pragma unroll
            for (int i = 0; i < 8; i++) {
                const int g = tid + i * 256;
                const int j = g & 63, dc = g >> 6;
                vreg[i] = *(const float4*)(Vsrc + (size_t)j * PD_ + dc * 4);
            }
        }

        // ---- S = Q @ K^T ----
        float sacc[8][4];
        #pragma unroll
        for (int nf = 0; nf < 8; nf++)
            #pragma unroll
            for (int r = 0; r < 4; r++) sacc[nf][r] = 0.0f;

        #pragma unroll
        for (int kf = 0; kf < 16; kf++) {
            uint32_t qa[4];
            ldsm4(qs_u + (uint32_t)(q_off + kf * 8) * 4, qa);
            #pragma unroll
            for (int nfp = 0; nfp < 4; nfp++) {
                uint32_t kb[4];
                ldsm4(kb_u + (uint32_t)(k_off + nfp * 16 * AQP + kf * 8) * 4, kb);
                mma_tf32u(sacc[2 * nfp],     qa, kb);
                mma_tf32u(sacc[2 * nfp + 1], qa, kb + 2);
            }
        }

        // ---- online softmax (warp-local rows lr, lr+8) ----
        #pragma unroll
        for (int nf = 0; nf < 8; nf++)
            #pragma unroll
            for (int r = 0; r < 4; r++) sacc[nf][r] *= SCALE;

        float m_t[2] = {-1e30f, -1e30f};
        #pragma unroll
        for (int nf = 0; nf < 8; nf++) {
            m_t[0] = fmaxf(m_t[0], fmaxf(sacc[nf][0], sacc[nf][1]));
            m_t[1] = fmaxf(m_t[1], fmaxf(sacc[nf][2], sacc[nf][3]));
        }
        #pragma unroll
        for (int off = 2; off >= 1; off >>= 1) {
            m_t[0] = fmaxf(m_t[0], __shfl_xor_sync(0xffffffffu, m_t[0], off));
            m_t[1] = fmaxf(m_t[1], __shfl_xor_sync(0xffffffffu, m_t[1], off));
        }
        float m_new[2], corr[2], lp[2] = {0.0f, 0.0f};
        #pragma unroll
        for (int r = 0; r < 2; r++) {
            m_new[r] = fmaxf(m_run[r], m_t[r]);
            corr[r] = __expf(m_run[r] - m_new[r]);
        }
        #pragma unroll
        for (int nf = 0; nf < 8; nf++) {
            #pragma unroll
            for (int r = 0; r < 4; r++) {
                const float e = __expf(sacc[nf][r] - m_new[r >> 1]);
                sacc[nf][r] = e;
                lp[r >> 1] += e;
            }
        }
        #pragma unroll
        for (int off = 2; off >= 1; off >>= 1) {
            lp[0] += __shfl_xor_sync(0xffffffffu, lp[0], off);
            lp[1] += __shfl_xor_sync(0xffffffffu, lp[1], off);
        }
        #pragma unroll
        for (int r = 0; r < 2; r++) {
            l_run[r] = l_run[r] * corr[r] + lp[r];
            m_run[r] = m_new[r];
        }
        #pragma unroll
        for (int nf = 0; nf < 16; nf++) {
            oacc[nf][0] *= corr[0]; oacc[nf][1] *= corr[0];
            oacc[nf][2] *= corr[1]; oacc[nf][3] *= corr[1];
        }

        // Fully-masked tile -> numerator contribution is zero; skip PV.
        const bool pv_skip = msk && (kbase + 63 <= qbase);
        if (!pv_skip) {
            const int rowg0 = qbase + r0w + lr;
            const int rowg1 = rowg0 + 8;
            #pragma unroll
            for (int nf = 0; nf < 8; nf++) {
                const int col = nf * 8 + 2 * lc;
                const int kidx = kbase + col;
                const bool z00 = msk && (kidx     <= rowg0);
                const bool z01 = msk && (kidx + 1 <= rowg0);
                const bool z10 = msk && (kidx     <= rowg1);
                const bool z11 = msk && (kidx + 1 <= rowg1);
                Ps[(r0w + lr) * APP + col]         = z00 ? 0.0f : to_tf32(sacc[nf][0]);
                Ps[(r0w + lr) * APP + col + 1]     = z01 ? 0.0f : to_tf32(sacc[nf][1]);
                Ps[(r0w + lr + 8) * APP + col]     = z10 ? 0.0f : to_tf32(sacc[nf][2]);
                Ps[(r0w + lr + 8) * APP + col + 1] = z11 ? 0.0f : to_tf32(sacc[nf][3]);
            }
            __syncwarp();

            // ---- O += P @ V ----
            #pragma unroll
            for (int jf = 0; jf < 8; jf++) {
                uint32_t pa[4];
                ldsm4(ps_u + (uint32_t)(p_off + jf * 8) * 4, pa);
                #pragma unroll
                for (int nfp = 0; nfp < 8; nfp++) {
                    uint32_t vb[4];
                    ldsm4(vt_u + (uint32_t)(v_off + nfp * 16 * AVP + jf * 8) * 4, vb);
                    mma_tf32u(oacc[2 * nfp],     pa, vb);
                    mma_tf32u(oacc[2 * nfp + 1], pa, vb + 2);
                }
            }
            __syncwarp();
        }
    }

    // Epilogue: unnormalized partial O + (m, l)
    float* Pog = g_po + ((size_t)(split * B_ + b) * LQ_ + qbase) * PD_;
    #pragma unroll
    for (int nf = 0; nf < 16; nf++) {
        const int row = r0w + lr;
        const int col = nf * 8 + 2 * lc;
        *(float2*)(Pog + (size_t)row * PD_ + col) =
            make_float2(oacc[nf][0], oacc[nf][1]);
        *(float2*)(Pog + (size_t)(row + 8) * PD_ + col) =
            make_float2(oacc[nf][2], oacc[nf][3]);
    }
    if (lc == 0) {
        float* mlg = g_ml + ((size_t)(split * B_ + b) * LQ_ + qbase) * 2;
        *(float2*)(mlg + (size_t)(r0w + lr) * 2)     = make_float2(m_run[0], l_run[0]);
        *(float2*)(mlg + (size_t)(r0w + lr + 8) * 2) = make_float2(m_run[1], l_run[1]);
    }
}

// ---------------------------------------------------------------------------
// Split-KV combine: out = (O0*e^{m0-m} + O1*e^{m1-m}) / (l0*e^{m0-m} + l1*e^{m1-m})
// ---------------------------------------------------------------------------
__global__ __launch_bounds__(256) void combine_kernel(float* __restrict__ out)
{
    const int idx = blockIdx.x * 256 + threadIdx.x;   // one float4 of out
    const int row = idx >> 5;                          // PD/4 = 32
    const int c4 = (idx & 31) * 4;

    const float2 ml0 = *(const float2*)(g_ml + (size_t)row * 2);
    const float2 ml1 = *(const float2*)(g_ml + ((size_t)B_ * LQ_ + row) * 2);
    const float m = fmaxf(ml0.x, ml1.x);
    const float w0 = __expf(ml0.x - m);
    const float w1 = __expf(ml1.x - m);
    const float inv = 1.0f / (ml0.y * w0 + ml1.y * w1);

    const float4 p0 = *(const float4*)(g_po + (size_t)row * PD_ + c4);
    const float4 p1 = *(const float4*)(g_po + ((size_t)B_ * LQ_ + row) * (size_t)PD_ + c4);
    float4 o;
    o.x = (p0.x * w0 + p1.x * w1) * inv;
    o.y = (p0.y * w0 + p1.y * w1) * inv;
    o.z = (p0.z * w0 + p1.z * w1) * inv;
    o.w = (p0.w * w0 + p1.w * w1) * inv;
    *(float4*)(out + (size_t)row * PD_ + c4) = o;
}

// ---------------------------------------------------------------------------
extern "C" void kernel_launch(void* const* d_in, const int* in_sizes, int n_in,
                              void* d_out, int out_size)
{
    const float* x  = (const float*)d_in[0];
    const float* y  = (const float*)d_in[1];
    const float* Wq = (const float*)d_in[2];
    const float* bq = (const float*)d_in[3];
    const float* Wk = (const float*)d_in[4];
    const float* bk = (const float*)d_in[5];
    const float* Wv = (const float*)d_in[6];
    const float* bv = (const float*)d_in[7];
    const int* maskp = (const int*)d_in[8];
    float* out = (float*)d_out;

    (void)in_sizes; (void)n_in; (void)out_size;

    cudaFuncSetAttribute(attn_kernel,
                         cudaFuncAttributeMaxDynamicSharedMemorySize, ATT_SMEM_BYTES);

    dim3 pg(64, 3);
    proj_kernel<<<pg, 256>>>(x, y, Wq, bq, Wk, bk, Wv, bv);

    dim3 ag(LQ_ / 128, B_, NSPLIT);
    attn_kernel<<<ag, 256, ATT_SMEM_BYTES>>>(maskp);

    combine_kernel<<<(B_ * LQ_ * PD_ / 4) / 256, 256>>>(out);
}

// round 5
// speedup vs baseline: 1.6869x; 1.6869x over previous
#include <cuda_runtime.h>
#include <cuda_pipeline.h>
#include <math.h>

#define B_   4
#define LQ_  2048
#define LK_  2048
#define XS_  1024
#define PD_  128

// Scratch for projected q/k/v (device globals: no allocation allowed).
// Values stored here are ALREADY rounded to TF32 (cvt.rna) so the attention
// kernel can cp.async them raw and the MMA truncation is lossless.
__device__ float g_q[B_ * LQ_ * PD_];
__device__ float g_k[B_ * LK_ * PD_];
__device__ float g_v[B_ * LK_ * PD_];

__device__ __forceinline__ float to_tf32(float x) {
    float r;
    asm("cvt.rna.tf32.f32 %0, %1;" : "=f"(r) : "f"(x));
    return r;
}

// D += A*B, m16n8k8 tf32. a: 4 regs, b: 2 regs, c: 4 fp32.
__device__ __forceinline__ void mma_tf32(float* c, const float* a, const float* b) {
    asm volatile(
        "mma.sync.aligned.m16n8k8.row.col.f32.tf32.tf32.f32 "
        "{%0,%1,%2,%3}, {%4,%5,%6,%7}, {%8,%9}, {%0,%1,%2,%3};\n"
        : "+f"(c[0]), "+f"(c[1]), "+f"(c[2]), "+f"(c[3])
        : "r"(__float_as_uint(a[0])), "r"(__float_as_uint(a[1])),
          "r"(__float_as_uint(a[2])), "r"(__float_as_uint(a[3])),
          "r"(__float_as_uint(b[0])), "r"(__float_as_uint(b[1])));
}

// ---------------------------------------------------------------------------
// Projection GEMM (tf32 tensor cores): C[8192,128] = A[8192,1024]@W[1024,128]+b
// grid (64, 3), 512 threads = 16 warps (4 m x 4 n), warp tile 32x32.
// Tile 128x128, BK=32. Register-staged prefetch overlaps LDG with MMA.
// Same (coalesced) load patterns and smem layouts as the R3 version; only the
// warp partitioning changed (8 -> 16 warps) to raise issue density per SMSP.
// As[m][k] pitch 36, Ws[k][n] pitch 136 -> conflict-free fragment reads.
// ---------------------------------------------------------------------------
#define PA_PITCH 36
#define PW_PITCH 136

__global__ __launch_bounds__(512) void proj_kernel(
    const float* __restrict__ x, const float* __restrict__ y,
    const float* __restrict__ Wq, const float* __restrict__ bq,
    const float* __restrict__ Wk, const float* __restrict__ bk,
    const float* __restrict__ Wv, const float* __restrict__ bv)
{
    const float* A; const float* W; const float* bias; float* C;
    if (blockIdx.y == 0)      { A = x; W = Wq; bias = bq; C = g_q; }
    else if (blockIdx.y == 1) { A = y; W = Wk; bias = bk; C = g_k; }
    else                      { A = y; W = Wv; bias = bv; C = g_v; }

    __shared__ float As[128 * PA_PITCH];   // [m][k], BK=32 cols used
    __shared__ float Ws[32 * PW_PITCH];    // [k][n]

    const int tid  = threadIdx.x;
    const int wid  = tid >> 5;
    const int lane = tid & 31;
    const int lr = lane >> 2, lc = lane & 3;
    const int rw = (wid & 3) * 32;   // warp row base within tile
    const int cw = (wid >> 2) * 32;  // warp col base within tile
    const int row0 = blockIdx.x * 128;

    // load indices (2 float4 each for A and W per chunk, 512 threads)
    // A: 128 rows x 8 float4 along k ; W: 32 k-rows x 32 float4 along n
    float4 rA[2], rW[2];
    #pragma unroll
    for (int i = 0; i < 2; i++) {
        const int g = tid + i * 512;
        rA[i] = *(const float4*)(A + (size_t)(row0 + (g >> 3)) * XS_ + (g & 7) * 4);
        rW[i] = *(const float4*)(W + (size_t)(g >> 5) * PD_ + (g & 31) * 4);
    }

    float acc[2][4][4];
    #pragma unroll
    for (int mf = 0; mf < 2; mf++)
        #pragma unroll
        for (int nf = 0; nf < 4; nf++)
            #pragma unroll
            for (int r = 0; r < 4; r++) acc[mf][nf][r] = 0.0f;

    for (int c = 0; c < 32; c++) {
        __syncthreads();
        #pragma unroll
        for (int i = 0; i < 2; i++) {
            const int g = tid + i * 512;
            const int ar = g >> 3, ak = (g & 7) * 4;
            As[ar * PA_PITCH + ak + 0] = to_tf32(rA[i].x);
            As[ar * PA_PITCH + ak + 1] = to_tf32(rA[i].y);
            As[ar * PA_PITCH + ak + 2] = to_tf32(rA[i].z);
            As[ar * PA_PITCH + ak + 3] = to_tf32(rA[i].w);
            const int wk = g >> 5, wn = (g & 31) * 4;
            Ws[wk * PW_PITCH + wn + 0] = to_tf32(rW[i].x);
            Ws[wk * PW_PITCH + wn + 1] = to_tf32(rW[i].y);
            Ws[wk * PW_PITCH + wn + 2] = to_tf32(rW[i].z);
            Ws[wk * PW_PITCH + wn + 3] = to_tf32(rW[i].w);
        }
        __syncthreads();

        if (c < 31) {
            const int k0 = (c + 1) * 32;
            #pragma unroll
            for (int i = 0; i < 2; i++) {
                const int g = tid + i * 512;
                rA[i] = *(const float4*)(A + (size_t)(row0 + (g >> 3)) * XS_ + k0 + (g & 7) * 4);
                rW[i] = *(const float4*)(W + (size_t)(k0 + (g >> 5)) * PD_ + (g & 31) * 4);
            }
        }

        #pragma unroll
        for (int kf = 0; kf < 4; kf++) {
            const int k = kf * 8;
            float a[2][4];
            #pragma unroll
            for (int mf = 0; mf < 2; mf++) {
                const int r = rw + mf * 16 + lr;
                a[mf][0] = As[r * PA_PITCH + k + lc];
                a[mf][1] = As[(r + 8) * PA_PITCH + k + lc];
                a[mf][2] = As[r * PA_PITCH + k + lc + 4];
                a[mf][3] = As[(r + 8) * PA_PITCH + k + lc + 4];
            }
            #pragma unroll
            for (int nf = 0; nf < 4; nf++) {
                float b[2];
                const int col = cw + nf * 8 + lr;
                b[0] = Ws[(k + lc) * PW_PITCH + col];
                b[1] = Ws[(k + lc + 4) * PW_PITCH + col];
                mma_tf32(acc[0][nf], a[0], b);
                mma_tf32(acc[1][nf], a[1], b);
            }
        }
    }

    // Epilogue: +bias, round to tf32, store
    #pragma unroll
    for (int mf = 0; mf < 2; mf++) {
        #pragma unroll
        for (int nf = 0; nf < 4; nf++) {
            const int row = row0 + rw + mf * 16 + lr;
            const int col = cw + nf * 8 + 2 * lc;
            const float2 bb = *(const float2*)(bias + col);
            float2 o0, o1;
            o0.x = to_tf32(acc[mf][nf][0] + bb.x);
            o0.y = to_tf32(acc[mf][nf][1] + bb.y);
            o1.x = to_tf32(acc[mf][nf][2] + bb.x);
            o1.y = to_tf32(acc[mf][nf][3] + bb.y);
            *(float2*)(C + (size_t)row * PD_ + col) = o0;
            *(float2*)(C + (size_t)(row + 8) * PD_ + col) = o1;
        }
    }
}

// ---------------------------------------------------------------------------
// Flash attention, tf32 mma, post-softmax triu(k=1) mask.  (R3 version, verbatim)
// grid (32, 4), 128 threads = 4 warps; each warp owns 16 full S-rows.
// cp.async double-buffered K/V tiles (values pre-rounded to tf32 by proj).
// smem pitches: Qs/Ks 132, Vs 136, Ps 68 -> conflict-free fragment reads.
// ---------------------------------------------------------------------------
#define BQ  64
#define BKT 64
#define QP  132
#define VP  136
#define PP  68
#define SMF_Q  0
#define SMF_K  (64 * QP)                       // 2 buffers of 64*132
#define SMF_V  (SMF_K + 2 * 64 * QP)           // 2 buffers of 64*136
#define SMF_P  (SMF_V + 2 * 64 * VP)
#define SMEM_FLOATS (SMF_P + 64 * PP)
#define SMEM_BYTES  (SMEM_FLOATS * 4)

__global__ __launch_bounds__(128) void attn_kernel(const int* __restrict__ maskp,
                                                   float* __restrict__ out)
{
    extern __shared__ float sm[];
    float* Qs = sm + SMF_Q;   // [r][d] pitch 132
    float* Ks = sm + SMF_K;   // buf*[j][d] pitch 132
    float* Vs = sm + SMF_V;   // buf*[j][d] pitch 136
    float* Ps = sm + SMF_P;   // [r][j] pitch 68

    const int b = blockIdx.y;
    const int qbase = blockIdx.x * BQ;
    const float* Qg = g_q + ((size_t)b * LQ_ + qbase) * PD_;
    const float* Kg = g_k + (size_t)b * LK_ * PD_;
    const float* Vg = g_v + (size_t)b * LK_ * PD_;

    const int tid  = threadIdx.x;
    const int wid  = tid >> 5;
    const int lane = tid & 31;
    const int lr = lane >> 2, lc = lane & 3;
    const int r0w = wid * 16;              // warp's S-row base
    const int msk = *maskp;
    const float SCALE = 0.0883883476483184f;  // 1/sqrt(128)

    // Prologue: async-copy Q + K/V tile 0 (one commit group)
    #pragma unroll
    for (int i = 0; i < 16; i++) {
        const int g = tid + i * 128;       // 2048 float4 per tile
        const int j = g >> 5, d4 = (g & 31) * 4;
        __pipeline_memcpy_async(&Qs[j * QP + d4], Qg + (size_t)j * PD_ + d4, 16);
        __pipeline_memcpy_async(&Ks[j * QP + d4], Kg + (size_t)j * PD_ + d4, 16);
        __pipeline_memcpy_async(&Vs[j * VP + d4], Vg + (size_t)j * PD_ + d4, 16);
    }
    __pipeline_commit();

    float oacc[16][4];
    #pragma unroll
    for (int nf = 0; nf < 16; nf++)
        #pragma unroll
        for (int r = 0; r < 4; r++) oacc[nf][r] = 0.0f;
    float m_run[2] = {-1e30f, -1e30f};
    float l_run[2] = {0.0f, 0.0f};

    for (int t = 0; t < LK_ / BKT; t++) {
        const int kbase = t * BKT;
        const int buf = t & 1;
        float* Kb = Ks + buf * 64 * QP;
        float* Vb = Vs + buf * 64 * VP;

        __pipeline_wait_prior(0);
        __syncthreads();

        if (t + 1 < LK_ / BKT) {
            const int nb = (t + 1) & 1;
            float* Kn = Ks + nb * 64 * QP;
            float* Vn = Vs + nb * 64 * VP;
            const float* Kgs = Kg + (size_t)(kbase + BKT) * PD_;
            const float* Vgs = Vg + (size_t)(kbase + BKT) * PD_;
            #pragma unroll
            for (int i = 0; i < 16; i++) {
                const int g = tid + i * 128;
                const int j = g >> 5, d4 = (g & 31) * 4;
                __pipeline_memcpy_async(&Kn[j * QP + d4], Kgs + (size_t)j * PD_ + d4, 16);
                __pipeline_memcpy_async(&Vn[j * VP + d4], Vgs + (size_t)j * PD_ + d4, 16);
            }
            __pipeline_commit();
        }

        // ---- S = Q @ K^T (each warp: 16 rows x 64 cols) ----
        float sacc[8][4];
        #pragma unroll
        for (int nf = 0; nf < 8; nf++)
            #pragma unroll
            for (int r = 0; r < 4; r++) sacc[nf][r] = 0.0f;

        #pragma unroll 4
        for (int kf = 0; kf < 16; kf++) {
            const int k = kf * 8;
            float a[4];
            a[0] = Qs[(r0w + lr) * QP + k + lc];
            a[1] = Qs[(r0w + lr + 8) * QP + k + lc];
            a[2] = Qs[(r0w + lr) * QP + k + lc + 4];
            a[3] = Qs[(r0w + lr + 8) * QP + k + lc + 4];
            #pragma unroll
            for (int nf = 0; nf < 8; nf++) {
                float bfr[2];
                bfr[0] = Kb[(nf * 8 + lr) * QP + k + lc];
                bfr[1] = Kb[(nf * 8 + lr) * QP + k + lc + 4];
                mma_tf32(sacc[nf], a, bfr);
            }
        }

        // ---- online softmax (warp-local; rows lr and lr+8 of this warp) ----
        #pragma unroll
        for (int nf = 0; nf < 8; nf++)
            #pragma unroll
            for (int r = 0; r < 4; r++) sacc[nf][r] *= SCALE;

        float m_t[2] = {-1e30f, -1e30f};
        #pragma unroll
        for (int nf = 0; nf < 8; nf++) {
            m_t[0] = fmaxf(m_t[0], fmaxf(sacc[nf][0], sacc[nf][1]));
            m_t[1] = fmaxf(m_t[1], fmaxf(sacc[nf][2], sacc[nf][3]));
        }
        #pragma unroll
        for (int off = 2; off >= 1; off >>= 1) {
            m_t[0] = fmaxf(m_t[0], __shfl_xor_sync(0xffffffffu, m_t[0], off));
            m_t[1] = fmaxf(m_t[1], __shfl_xor_sync(0xffffffffu, m_t[1], off));
        }
        float m_new[2], corr[2], lp[2] = {0.0f, 0.0f};
        #pragma unroll
        for (int r = 0; r < 2; r++) {
            m_new[r] = fmaxf(m_run[r], m_t[r]);
            corr[r] = __expf(m_run[r] - m_new[r]);
        }
        #pragma unroll
        for (int nf = 0; nf < 8; nf++) {
            #pragma unroll
            for (int r = 0; r < 4; r++) {
                const float e = __expf(sacc[nf][r] - m_new[r >> 1]);
                sacc[nf][r] = e;
                lp[r >> 1] += e;
            }
        }
        #pragma unroll
        for (int off = 2; off >= 1; off >>= 1) {
            lp[0] += __shfl_xor_sync(0xffffffffu, lp[0], off);
            lp[1] += __shfl_xor_sync(0xffffffffu, lp[1], off);
        }
        #pragma unroll
        for (int r = 0; r < 2; r++) {
            l_run[r] = l_run[r] * corr[r] + lp[r];
            m_run[r] = m_new[r];
        }
        #pragma unroll
        for (int nf = 0; nf < 16; nf++) {
            oacc[nf][0] *= corr[0]; oacc[nf][1] *= corr[0];
            oacc[nf][2] *= corr[1]; oacc[nf][3] *= corr[1];
        }

        // Tile fully below/at diagonal for every row of this CTA -> P == 0
        const bool pv_skip = msk && (kbase + BKT - 1 <= qbase);
        if (!pv_skip) {
            // masked P -> smem (tf32-rounded)
            const int rowg0 = qbase + r0w + lr;
            const int rowg1 = rowg0 + 8;
            #pragma unroll
            for (int nf = 0; nf < 8; nf++) {
                const int col = nf * 8 + 2 * lc;
                const int kidx = kbase + col;
                const bool z00 = msk && (kidx     <= rowg0);
                const bool z01 = msk && (kidx + 1 <= rowg0);
                const bool z10 = msk && (kidx     <= rowg1);
                const bool z11 = msk && (kidx + 1 <= rowg1);
                Ps[(r0w + lr) * PP + col]     = z00 ? 0.0f : to_tf32(sacc[nf][0]);
                Ps[(r0w + lr) * PP + col + 1] = z01 ? 0.0f : to_tf32(sacc[nf][1]);
                Ps[(r0w + lr + 8) * PP + col]     = z10 ? 0.0f : to_tf32(sacc[nf][2]);
                Ps[(r0w + lr + 8) * PP + col + 1] = z11 ? 0.0f : to_tf32(sacc[nf][3]);
            }
            __syncwarp();

            // ---- O += P @ V ----
            #pragma unroll 2
            for (int jf = 0; jf < 8; jf++) {
                const int j = jf * 8;
                float a[4];
                a[0] = Ps[(r0w + lr) * PP + j + lc];
                a[1] = Ps[(r0w + lr + 8) * PP + j + lc];
                a[2] = Ps[(r0w + lr) * PP + j + lc + 4];
                a[3] = Ps[(r0w + lr + 8) * PP + j + lc + 4];
                #pragma unroll
                for (int nf = 0; nf < 16; nf++) {
                    float bfr[2];
                    bfr[0] = Vb[(j + lc) * VP + nf * 8 + lr];
                    bfr[1] = Vb[(j + lc + 4) * VP + nf * 8 + lr];
                    mma_tf32(oacc[nf], a, bfr);
                }
            }
            __syncwarp();
        }
    }

    // Epilogue: normalize by full denominator, store
    float* Og = out + ((size_t)b * LQ_ + qbase) * PD_;
    const float inv0 = 1.0f / l_run[0];
    const float inv1 = 1.0f / l_run[1];
    #pragma unroll
    for (int nf = 0; nf < 16; nf++) {
        const int row = r0w + lr;
        const int col = nf * 8 + 2 * lc;
        float2 o0 = make_float2(oacc[nf][0] * inv0, oacc[nf][1] * inv0);
        float2 o1 = make_float2(oacc[nf][2] * inv1, oacc[nf][3] * inv1);
        *(float2*)(Og + (size_t)row * PD_ + col) = o0;
        *(float2*)(Og + (size_t)(row + 8) * PD_ + col) = o1;
    }
}

// ---------------------------------------------------------------------------
extern "C" void kernel_launch(void* const* d_in, const int* in_sizes, int n_in,
                              void* d_out, int out_size)
{
    const float* x  = (const float*)d_in[0];
    const float* y  = (const float*)d_in[1];
    const float* Wq = (const float*)d_in[2];
    const float* bq = (const float*)d_in[3];
    const float* Wk = (const float*)d_in[4];
    const float* bk = (const float*)d_in[5];
    const float* Wv = (const float*)d_in[6];
    const float* bv = (const float*)d_in[7];
    const int* maskp = (const int*)d_in[8];
    float* out = (float*)d_out;

    (void)in_sizes; (void)n_in; (void)out_size;

    cudaFuncSetAttribute(attn_kernel,
                         cudaFuncAttributeMaxDynamicSharedMemorySize, SMEM_BYTES);

    dim3 pg(64, 3);
    proj_kernel<<<pg, 512>>>(x, y, Wq, bq, Wk, bk, Wv, bv);

    dim3 ag(LQ_ / BQ, B_);
    attn_kernel<<<ag, 128, SMEM_BYTES>>>(maskp, out);
}